// round 7
// baseline (speedup 1.0000x reference)
#include <cuda_runtime.h>

#define OBS_LEN 8
#define PRED_LEN 12
#define BATCHN 65536
#define HID 64
#define NG 256           // 4*HID gates
#define BLK 256          // threads per block
#define EPB 256          // batch elements per block (1 per thread)

// Precomputed per-phase (0=encoder, 1=decoder) parameters:
//   g_cm[ph][0..255]    = Mx[j]   (input-x combined weight)
//   g_cm[ph][256..511]  = My[j]
//   g_cm[ph][512..767]  = CB[j]   = w_ih@emb_b + b_ih + b_hh
//   g_wT[ph][k*256 + j] = w_hh[j][k]  (transposed recurrent weights)
__device__ float g_cm[2][768];
__device__ float g_wT[2][HID * NG];
// c-state scratch: [unit][batch], thread-private columns, L2-resident (16 MB)
__device__ float g_cS[HID * BATCHN];

// ---------------------------------------------------------------------------
// f32x2 helpers (Blackwell packed fp32 FMA)
// ---------------------------------------------------------------------------
__device__ __forceinline__ unsigned long long pack2(float x, float y) {
    unsigned long long r;
    asm("mov.b64 %0, {%1, %2};" : "=l"(r) : "f"(x), "f"(y));
    return r;
}
__device__ __forceinline__ void fma2(unsigned long long& d,
                                     unsigned long long a,
                                     unsigned long long b) {
    asm("fma.rn.f32x2 %0, %1, %2, %0;" : "+l"(d) : "l"(a), "l"(b));
}
__device__ __forceinline__ float2 unpack2(unsigned long long v) {
    float2 r;
    asm("mov.b64 {%0, %1}, %2;" : "=f"(r.x), "=f"(r.y) : "l"(v));
    return r;
}

// Fast activations (MUFU; rel err ~1e-6)
__device__ __forceinline__ float fsig(float x) {
    return __fdividef(1.0f, 1.0f + __expf(-x));
}
__device__ __forceinline__ float ftanh_(float x) {
    return 1.0f - 2.0f * __fdividef(1.0f, 1.0f + __expf(2.0f * x));
}

// ---------------------------------------------------------------------------
// Prep kernel: fold embedding into input-projection, transpose w_hh
// ---------------------------------------------------------------------------
__global__ void vlstm_prep(const float* __restrict__ ew, const float* __restrict__ eb,
                           const float* __restrict__ wih_e, const float* __restrict__ whh_e,
                           const float* __restrict__ bih_e, const float* __restrict__ bhh_e,
                           const float* __restrict__ dw, const float* __restrict__ db,
                           const float* __restrict__ wih_d, const float* __restrict__ whh_d,
                           const float* __restrict__ bih_d, const float* __restrict__ bhh_d)
{
    int j = threadIdx.x;  // 0..255 = gate row
    for (int ph = 0; ph < 2; ph++) {
        const float* emb_w = ph ? dw : ew;
        const float* emb_b = ph ? db : eb;
        const float* wih   = ph ? wih_d : wih_e;
        const float* whh   = ph ? whh_d : whh_e;
        const float* bih   = ph ? bih_d : bih_e;
        const float* bhh   = ph ? bhh_d : bhh_e;
        float mx = 0.f, my = 0.f, mb = 0.f;
        #pragma unroll 8
        for (int e = 0; e < 64; e++) {
            float wv = wih[j * 64 + e];
            mx += wv * emb_w[e * 2 + 0];
            my += wv * emb_w[e * 2 + 1];
            mb += wv * emb_b[e];
        }
        g_cm[ph][j]       = mx;
        g_cm[ph][256 + j] = my;
        g_cm[ph][512 + j] = mb + bih[j] + bhh[j];
        #pragma unroll 8
        for (int k = 0; k < 64; k++)
            g_wT[ph][k * NG + j] = whh[j * 64 + k];
    }
}

// ---------------------------------------------------------------------------
// One LSTM step for this thread's batch element.
// Hidden units processed in 4 groups of 16 (acc = 32 u64 = 64 regs).
// c lives in global scratch (cG = &g_cS[b]), prefetched per group.
// h columns are thread-private shared slots — no syncs in the time loop.
// ---------------------------------------------------------------------------
template <bool DEC>
__device__ __forceinline__ void lstm_step1(
    const float* __restrict__ sWT, const float* __restrict__ sCM,
    const float* __restrict__ hcur, float* __restrict__ hnxt,
    float* __restrict__ cG, int tid, float px, float py,
    const float* __restrict__ sP0, const float* __restrict__ sP1,
    float& rx, float& ry)
{
    const unsigned long long px2 = pack2(px, px);
    const unsigned long long py2 = pack2(py, py);

    #pragma unroll 1
    for (int grp = 0; grp < 4; grp++) {
        const int m = grp * 16;   // hidden units m..m+15

        // Prefetch c for this group's units (global/L2; hidden by matvec)
        float cpre[16];
        #pragma unroll
        for (int i = 0; i < 16; i++)
            cpre[i] = cG[(m + i) * BATCHN];

        // init accumulators: CB + M * pos
        unsigned long long acc[32];  // [gate_type 4][pair 8]
        #pragma unroll
        for (int gt = 0; gt < 4; gt++) {
            #pragma unroll
            for (int p = 0; p < 8; p++) {
                int j = gt * 64 + m + 2 * p;
                unsigned long long a = *(const unsigned long long*)(sCM + 512 + j);
                fma2(a, *(const unsigned long long*)(sCM + j),       px2);
                fma2(a, *(const unsigned long long*)(sCM + 256 + j), py2);
                acc[gt * 8 + p] = a;
            }
        }

        // recurrent matvec: gates += w_hh^T[k][...] * h[k]
        const float* hp = hcur + tid;
        #pragma unroll 4
        for (int k = 0; k < 64; k++) {
            float hk = hp[k * EPB];
            unsigned long long h2 = pack2(hk, hk);
            const float* wr = sWT + k * NG + m;
            #pragma unroll
            for (int gt = 0; gt < 4; gt++) {
                ulonglong2 w0 = *(const ulonglong2*)(wr + gt * 64);
                ulonglong2 w1 = *(const ulonglong2*)(wr + gt * 64 + 4);
                ulonglong2 w2 = *(const ulonglong2*)(wr + gt * 64 + 8);
                ulonglong2 w3 = *(const ulonglong2*)(wr + gt * 64 + 12);
                fma2(acc[gt * 8 + 0], w0.x, h2);
                fma2(acc[gt * 8 + 1], w0.y, h2);
                fma2(acc[gt * 8 + 2], w1.x, h2);
                fma2(acc[gt * 8 + 3], w1.y, h2);
                fma2(acc[gt * 8 + 4], w2.x, h2);
                fma2(acc[gt * 8 + 5], w2.y, h2);
                fma2(acc[gt * 8 + 6], w3.x, h2);
                fma2(acc[gt * 8 + 7], w3.y, h2);
            }
        }

        // activations + state update for units m..m+15
        #pragma unroll
        for (int p = 0; p < 8; p++) {
            float2 iv = unpack2(acc[0 * 8 + p]);
            float2 fv = unpack2(acc[1 * 8 + p]);
            float2 gv = unpack2(acc[2 * 8 + p]);
            float2 ov = unpack2(acc[3 * 8 + p]);
            int u = m + 2 * p;
            {
                float cn = fmaf(fsig(fv.x), cpre[2 * p], fsig(iv.x) * ftanh_(gv.x));
                cG[u * BATCHN] = cn;
                float hn = fsig(ov.x) * ftanh_(cn);
                hnxt[u * EPB + tid] = hn;
                if (DEC) { rx = fmaf(hn, sP0[u], rx); ry = fmaf(hn, sP1[u], ry); }
            }
            {
                float cn = fmaf(fsig(fv.y), cpre[2 * p + 1], fsig(iv.y) * ftanh_(gv.y));
                cG[(u + 1) * BATCHN] = cn;
                float hn = fsig(ov.y) * ftanh_(cn);
                hnxt[(u + 1) * EPB + tid] = hn;
                if (DEC) { rx = fmaf(hn, sP0[u + 1], rx); ry = fmaf(hn, sP1[u + 1], ry); }
            }
        }
    }
}

// Shared layout (floats):
//   [0,16384)       sWT  (current phase recurrent weights, transposed)
//   [16384,17152)   sCM  (Mx | My | CB)
//   [17152,17216)   sP0 ; [17216,17280) sP1 ; pad to 17408
//   [17408,+16384)  hA ; then hB
#define SM_FLOATS (17408 + 2 * HID * EPB)   // 50176 floats = 200704 B

__global__ void __launch_bounds__(BLK, 1)
vlstm_main(const float* __restrict__ obs_rel,
           const float* __restrict__ h2p_w, const float* __restrict__ h2p_b,
           float* __restrict__ out)
{
    extern __shared__ float sm[];
    float* sWT = sm;
    float* sCM = sm + 16384;
    float* sP0 = sm + 17152;
    float* sP1 = sm + 17216;
    float* hA  = sm + 17408;
    float* hB  = hA + HID * EPB;

    const int tid = threadIdx.x;
    const int b   = blockIdx.x * EPB + tid;
    float* cG = g_cS + b;

    // ---- load encoder-phase weights + cm + h2p ----
    {
        const float4* src = (const float4*)g_wT[0];
        float4* dst = (float4*)sWT;
        for (int i = tid; i < HID * NG / 4; i += BLK) dst[i] = src[i];
        for (int i = tid; i < 768; i += BLK) sCM[i] = g_cm[0][i];
        if (tid < 64) { sP0[tid] = h2p_w[tid]; sP1[tid] = h2p_w[64 + tid]; }
    }
    #pragma unroll
    for (int u = 0; u < HID; u++) {
        hA[u * EPB + tid] = 0.f;
        cG[u * BATCHN]    = 0.f;
    }
    __syncthreads();

    float dum = 0.f;
    float* hc = hA;
    float* hn = hB;

    // ---- encoder: 8 steps ----
    #pragma unroll 1
    for (int t = 0; t < OBS_LEN; t++) {
        float2 pos = *(const float2*)(obs_rel + (size_t)(t * BATCHN + b) * 2);
        lstm_step1<false>(sWT, sCM, hc, hn, cG, tid, pos.x, pos.y,
                          sP0, sP1, dum, dum);
        float* tmp = hn; hn = hc; hc = tmp;
    }

    // ---- swap in decoder-phase weights, reset c ----
    __syncthreads();
    {
        const float4* src = (const float4*)g_wT[1];
        float4* dst = (float4*)sWT;
        for (int i = tid; i < HID * NG / 4; i += BLK) dst[i] = src[i];
        for (int i = tid; i < 768; i += BLK) sCM[i] = g_cm[1][i];
    }
    #pragma unroll
    for (int u = 0; u < HID; u++)
        cG[u * BATCHN] = 0.f;   // decoder c0 = 0
    __syncthreads();

    const float pb0 = h2p_b[0], pb1 = h2p_b[1];
    float2 rel = *(const float2*)(obs_rel + (size_t)(7 * BATCHN + b) * 2);

    // ---- decoder: 12 steps, autoregressive through h2p ----
    #pragma unroll 1
    for (int t = 0; t < PRED_LEN; t++) {
        float rx = pb0, ry = pb1;
        lstm_step1<true>(sWT, sCM, hc, hn, cG, tid, rel.x, rel.y,
                         sP0, sP1, rx, ry);
        float* tmp = hn; hn = hc; hc = tmp;
        rel.x = rx; rel.y = ry;
        *(float2*)(out + (size_t)(t * BATCHN + b) * 2) = rel;
    }
}

// ---------------------------------------------------------------------------
// Launch
// ---------------------------------------------------------------------------
extern "C" void kernel_launch(void* const* d_in, const int* in_sizes, int n_in,
                              void* d_out, int out_size)
{
    // metadata order: 0 obs_traj(unused), 1 obs_traj_rel,
    // 2..7 enc{emb_w,emb_b,w_ih,w_hh,b_ih,b_hh}, 8..13 dec{...}, 14 h2p_w, 15 h2p_b
    const float* obs_rel = (const float*)d_in[1];

    vlstm_prep<<<1, 256>>>(
        (const float*)d_in[2],  (const float*)d_in[3],
        (const float*)d_in[4],  (const float*)d_in[5],
        (const float*)d_in[6],  (const float*)d_in[7],
        (const float*)d_in[8],  (const float*)d_in[9],
        (const float*)d_in[10], (const float*)d_in[11],
        (const float*)d_in[12], (const float*)d_in[13]);

    const size_t smem = (size_t)SM_FLOATS * sizeof(float);   // ~196 KB
    cudaFuncSetAttribute(vlstm_main, cudaFuncAttributeMaxDynamicSharedMemorySize, (int)smem);
    vlstm_main<<<BATCHN / EPB, BLK, smem>>>(
        obs_rel, (const float*)d_in[14], (const float*)d_in[15], (float*)d_out);
}

// round 8
// speedup vs baseline: 1.5313x; 1.5313x over previous
#include <cuda_runtime.h>

#define OBS_LEN 8
#define PRED_LEN 12
#define BATCHN 65536
#define HID 64
#define NG 256           // 4*HID gates
#define BLK 256          // threads per block (8 warps, 2 per SMSP)
#define EPB 512          // batch elements per block (2 per thread) -> grid=128, single wave

// Precomputed per-phase (0=encoder, 1=decoder) parameters:
//   g_cm[ph][0..255]    = Mx[j]   (input-x combined weight)
//   g_cm[ph][256..511]  = My[j]
//   g_cm[ph][512..767]  = CB[j]   = w_ih@emb_b + b_ih + b_hh
//   g_wT[ph][k*256 + j] = w_hh[j][k]  (transposed recurrent weights)
__device__ float g_cm[2][768];
__device__ float g_wT[2][HID * NG];
// state scratch: [unit][batch], thread-private columns, L2/L1-resident
__device__ float g_cS[HID * BATCHN];          // c state (16 MB)
__device__ float g_h[2][HID * BATCHN];        // h ping-pong (2 x 16 MB)

// ---------------------------------------------------------------------------
// f32x2 helpers (Blackwell packed fp32 FMA)
// ---------------------------------------------------------------------------
__device__ __forceinline__ unsigned long long pack2(float x, float y) {
    unsigned long long r;
    asm("mov.b64 %0, {%1, %2};" : "=l"(r) : "f"(x), "f"(y));
    return r;
}
__device__ __forceinline__ void fma2(unsigned long long& d,
                                     unsigned long long a,
                                     unsigned long long b) {
    asm("fma.rn.f32x2 %0, %1, %2, %0;" : "+l"(d) : "l"(a), "l"(b));
}
__device__ __forceinline__ float2 unpack2(unsigned long long v) {
    float2 r;
    asm("mov.b64 {%0, %1}, %2;" : "=f"(r.x), "=f"(r.y) : "l"(v));
    return r;
}

// HW tanh (MUFU.TANH, sm_75+); sigmoid via exact identity -> 1 MUFU each
__device__ __forceinline__ float tha(float x) {
    float r; asm("tanh.approx.f32 %0, %1;" : "=f"(r) : "f"(x)); return r;
}
__device__ __forceinline__ float sga(float x) {
    return fmaf(0.5f, tha(0.5f * x), 0.5f);
}

// ---------------------------------------------------------------------------
// Prep kernel: fold embedding into input-projection, transpose w_hh
// ---------------------------------------------------------------------------
__global__ void vlstm_prep(const float* __restrict__ ew, const float* __restrict__ eb,
                           const float* __restrict__ wih_e, const float* __restrict__ whh_e,
                           const float* __restrict__ bih_e, const float* __restrict__ bhh_e,
                           const float* __restrict__ dw, const float* __restrict__ db,
                           const float* __restrict__ wih_d, const float* __restrict__ whh_d,
                           const float* __restrict__ bih_d, const float* __restrict__ bhh_d)
{
    int j = threadIdx.x;  // 0..255 = gate row
    for (int ph = 0; ph < 2; ph++) {
        const float* emb_w = ph ? dw : ew;
        const float* emb_b = ph ? db : eb;
        const float* wih   = ph ? wih_d : wih_e;
        const float* whh   = ph ? whh_d : whh_e;
        const float* bih   = ph ? bih_d : bih_e;
        const float* bhh   = ph ? bhh_d : bhh_e;
        float mx = 0.f, my = 0.f, mb = 0.f;
        #pragma unroll 8
        for (int e = 0; e < 64; e++) {
            float wv = wih[j * 64 + e];
            mx += wv * emb_w[e * 2 + 0];
            my += wv * emb_w[e * 2 + 1];
            mb += wv * emb_b[e];
        }
        g_cm[ph][j]       = mx;
        g_cm[ph][256 + j] = my;
        g_cm[ph][512 + j] = mb + bih[j] + bhh[j];
        #pragma unroll 8
        for (int k = 0; k < 64; k++)
            g_wT[ph][k * NG + j] = whh[j * 64 + k];
    }
}

// ---------------------------------------------------------------------------
// One LSTM step for this thread's TWO batch elements (A, B = b0, b0+1).
// hO/hN/cG are global pointers pre-offset by b0; columns are thread-private
// (no syncs anywhere in the time loop). 8 groups of 8 hidden units:
// acc = 32 u64 = 64 regs. h reads are L1-resident after group 0.
// ---------------------------------------------------------------------------
template <bool DEC>
__device__ __forceinline__ void lstm_step2(
    const float* __restrict__ sWT, const float* __restrict__ sCM,
    const float* __restrict__ hO, float* __restrict__ hN,
    float* __restrict__ cG,
    float pxA, float pyA, float pxB, float pyB,
    const float* __restrict__ sP0, const float* __restrict__ sP1,
    float& rxA, float& ryA, float& rxB, float& ryB)
{
    const unsigned long long pxA2 = pack2(pxA, pxA);
    const unsigned long long pyA2 = pack2(pyA, pyA);
    const unsigned long long pxB2 = pack2(pxB, pxB);
    const unsigned long long pyB2 = pack2(pyB, pyB);

    #pragma unroll 1
    for (int grp = 0; grp < 8; grp++) {
        const int m = grp * 8;   // hidden units m..m+7

        // Prefetch c for this group's 8 units (L2/L1; hidden by matvec)
        float2 cpre[8];
        #pragma unroll
        for (int i = 0; i < 8; i++)
            cpre[i] = *(const float2*)(cG + (m + i) * BATCHN);

        // init accumulators: CB + M * pos
        unsigned long long aA[16], aB[16];  // [gate_type 4][pair 4]
        #pragma unroll
        for (int gt = 0; gt < 4; gt++) {
            #pragma unroll
            for (int p = 0; p < 4; p++) {
                int j = gt * 64 + m + 2 * p;
                unsigned long long mx = *(const unsigned long long*)(sCM + j);
                unsigned long long my = *(const unsigned long long*)(sCM + 256 + j);
                unsigned long long cb = *(const unsigned long long*)(sCM + 512 + j);
                unsigned long long tA = cb, tB = cb;
                fma2(tA, mx, pxA2); fma2(tA, my, pyA2);
                fma2(tB, mx, pxB2); fma2(tB, my, pyB2);
                aA[gt * 4 + p] = tA;
                aB[gt * 4 + p] = tB;
            }
        }

        // recurrent matvec: each weight LDS.128 feeds 4 FFMA2 (2 elements)
        #pragma unroll 8
        for (int k = 0; k < 64; k++) {
            float2 hv = *(const float2*)(hO + k * BATCHN);    // h[k] for A,B
            unsigned long long h2A = pack2(hv.x, hv.x);
            unsigned long long h2B = pack2(hv.y, hv.y);
            const float* wr = sWT + k * NG + m;
            #pragma unroll
            for (int gt = 0; gt < 4; gt++) {
                ulonglong2 w01 = *(const ulonglong2*)(wr + gt * 64);
                ulonglong2 w23 = *(const ulonglong2*)(wr + gt * 64 + 4);
                fma2(aA[gt * 4 + 0], w01.x, h2A); fma2(aB[gt * 4 + 0], w01.x, h2B);
                fma2(aA[gt * 4 + 1], w01.y, h2A); fma2(aB[gt * 4 + 1], w01.y, h2B);
                fma2(aA[gt * 4 + 2], w23.x, h2A); fma2(aB[gt * 4 + 2], w23.x, h2B);
                fma2(aA[gt * 4 + 3], w23.y, h2A); fma2(aB[gt * 4 + 3], w23.y, h2B);
            }
        }

        // activations + state update for units m..m+7, both elements
        #pragma unroll
        for (int p = 0; p < 4; p++) {
            float2 iA = unpack2(aA[0  + p]), iB = unpack2(aB[0  + p]);
            float2 fA = unpack2(aA[4  + p]), fB = unpack2(aB[4  + p]);
            float2 gA = unpack2(aA[8  + p]), gB = unpack2(aB[8  + p]);
            float2 oA = unpack2(aA[12 + p]), oB = unpack2(aB[12 + p]);
            int u = m + 2 * p;
            {   // unit u  (x lanes)
                float2 cv = cpre[2 * p];
                float cnA = fmaf(sga(fA.x), cv.x, sga(iA.x) * tha(gA.x));
                float cnB = fmaf(sga(fB.x), cv.y, sga(iB.x) * tha(gB.x));
                *(float2*)(cG + u * BATCHN) = make_float2(cnA, cnB);
                float hnA = sga(oA.x) * tha(cnA);
                float hnB = sga(oB.x) * tha(cnB);
                *(float2*)(hN + u * BATCHN) = make_float2(hnA, hnB);
                if (DEC) {
                    rxA = fmaf(hnA, sP0[u], rxA); ryA = fmaf(hnA, sP1[u], ryA);
                    rxB = fmaf(hnB, sP0[u], rxB); ryB = fmaf(hnB, sP1[u], ryB);
                }
            }
            {   // unit u+1 (y lanes)
                float2 cv = cpre[2 * p + 1];
                float cnA = fmaf(sga(fA.y), cv.x, sga(iA.y) * tha(gA.y));
                float cnB = fmaf(sga(fB.y), cv.y, sga(iB.y) * tha(gB.y));
                *(float2*)(cG + (u + 1) * BATCHN) = make_float2(cnA, cnB);
                float hnA = sga(oA.y) * tha(cnA);
                float hnB = sga(oB.y) * tha(cnB);
                *(float2*)(hN + (u + 1) * BATCHN) = make_float2(hnA, hnB);
                if (DEC) {
                    rxA = fmaf(hnA, sP0[u + 1], rxA); ryA = fmaf(hnA, sP1[u + 1], ryA);
                    rxB = fmaf(hnB, sP0[u + 1], rxB); ryB = fmaf(hnB, sP1[u + 1], ryB);
                }
            }
        }
    }
}

// Shared layout (floats): sWT[16384] | sCM[768] | sP0[64] | sP1[64]
#define SM_FLOATS (16384 + 768 + 64 + 64)   // 17280 floats = 69120 B

__global__ void __launch_bounds__(BLK, 1)
vlstm_main(const float* __restrict__ obs_rel,
           const float* __restrict__ h2p_w, const float* __restrict__ h2p_b,
           float* __restrict__ out)
{
    extern __shared__ float sm[];
    float* sWT = sm;
    float* sCM = sm + 16384;
    float* sP0 = sm + 17152;
    float* sP1 = sm + 17216;

    const int tid = threadIdx.x;
    const int b0  = blockIdx.x * EPB + 2 * tid;   // this thread's element pair
    float* cG  = g_cS + b0;
    float* h0p = g_h[0] + b0;
    float* h1p = g_h[1] + b0;

    // ---- load encoder-phase weights + cm + h2p ----
    {
        const float4* src = (const float4*)g_wT[0];
        float4* dst = (float4*)sWT;
        for (int i = tid; i < HID * NG / 4; i += BLK) dst[i] = src[i];
        for (int i = tid; i < 768; i += BLK) sCM[i] = g_cm[0][i];
        if (tid < 64) { sP0[tid] = h2p_w[tid]; sP1[tid] = h2p_w[64 + tid]; }
    }
    #pragma unroll
    for (int u = 0; u < HID; u++) {
        *(float2*)(h0p + u * BATCHN) = make_float2(0.f, 0.f);
        *(float2*)(cG  + u * BATCHN) = make_float2(0.f, 0.f);
    }
    __syncthreads();

    float dum = 0.f;
    float* hc = h0p;   // current (old) h buffer
    float* hn = h1p;   // next (new) h buffer

    // ---- encoder: 8 steps ----
    #pragma unroll 1
    for (int t = 0; t < OBS_LEN; t++) {
        float4 pos = *(const float4*)(obs_rel + (size_t)(t * BATCHN + b0) * 2);
        lstm_step2<false>(sWT, sCM, hc, hn, cG,
                          pos.x, pos.y, pos.z, pos.w,
                          sP0, sP1, dum, dum, dum, dum);
        float* tmp = hn; hn = hc; hc = tmp;
    }

    // ---- swap in decoder-phase weights, reset c ----
    __syncthreads();
    {
        const float4* src = (const float4*)g_wT[1];
        float4* dst = (float4*)sWT;
        for (int i = tid; i < HID * NG / 4; i += BLK) dst[i] = src[i];
        for (int i = tid; i < 768; i += BLK) sCM[i] = g_cm[1][i];
    }
    #pragma unroll
    for (int u = 0; u < HID; u++)
        *(float2*)(cG + u * BATCHN) = make_float2(0.f, 0.f);  // decoder c0 = 0
    __syncthreads();

    const float pb0 = h2p_b[0], pb1 = h2p_b[1];
    float4 rel = *(const float4*)(obs_rel + (size_t)(7 * BATCHN + b0) * 2);

    // ---- decoder: 12 steps, autoregressive through h2p ----
    #pragma unroll 1
    for (int t = 0; t < PRED_LEN; t++) {
        float rxA = pb0, ryA = pb1, rxB = pb0, ryB = pb1;
        lstm_step2<true>(sWT, sCM, hc, hn, cG,
                         rel.x, rel.y, rel.z, rel.w,
                         sP0, sP1, rxA, ryA, rxB, ryB);
        float* tmp = hn; hn = hc; hc = tmp;
        rel = make_float4(rxA, ryA, rxB, ryB);
        *(float4*)(out + (size_t)(t * BATCHN + b0) * 2) = rel;
    }
}

// ---------------------------------------------------------------------------
// Launch
// ---------------------------------------------------------------------------
extern "C" void kernel_launch(void* const* d_in, const int* in_sizes, int n_in,
                              void* d_out, int out_size)
{
    // metadata order: 0 obs_traj(unused), 1 obs_traj_rel,
    // 2..7 enc{emb_w,emb_b,w_ih,w_hh,b_ih,b_hh}, 8..13 dec{...}, 14 h2p_w, 15 h2p_b
    const float* obs_rel = (const float*)d_in[1];

    vlstm_prep<<<1, 256>>>(
        (const float*)d_in[2],  (const float*)d_in[3],
        (const float*)d_in[4],  (const float*)d_in[5],
        (const float*)d_in[6],  (const float*)d_in[7],
        (const float*)d_in[8],  (const float*)d_in[9],
        (const float*)d_in[10], (const float*)d_in[11],
        (const float*)d_in[12], (const float*)d_in[13]);

    const size_t smem = (size_t)SM_FLOATS * sizeof(float);   // ~69 KB
    cudaFuncSetAttribute(vlstm_main, cudaFuncAttributeMaxDynamicSharedMemorySize, (int)smem);
    vlstm_main<<<BATCHN / EPB, BLK, smem>>>(
        obs_rel, (const float*)d_in[14], (const float*)d_in[15], (float*)d_out);
}

// round 10
// speedup vs baseline: 3.5732x; 2.3335x over previous
#include <cuda_runtime.h>
#include <cstdint>

#define OBS_LEN 8
#define PRED_LEN 12
#define BATCHN 65536
#define HID 64
#define BLK 256
#define EPB 256          // elems per CTA -> grid = 256
#define HSTR 72          // h tile row stride (floats): 64 h + px,py,1,zeros
#define WF_N 18432       // frag words/phase: 16 chunks * 2 tiles * 9 ksteps * 64

// W in mma-B-fragment order (tf32 bits), per phase; c state scratch
__device__ uint32_t g_wF[2][WF_N];
__device__ float    g_cS[HID * BATCHN];

// ---- smem float-offsets ----
#define SF_WF 0              // 18432 (73728 B)
#define SF_H0 18432          // 256*72
#define SF_H1 36864
#define SF_P0 55296          // 64
#define SF_P1 55360          // 64
#define SF_TOT 55424         // *4 = 221696 B

static __device__ __forceinline__ float tha(float x){
    float r; asm("tanh.approx.f32 %0, %1;" : "=f"(r) : "f"(x)); return r;
}
static __device__ __forceinline__ float sga(float x){
    return fmaf(0.5f, tha(0.5f * x), 0.5f);
}
static __device__ __forceinline__ uint32_t t32(float x){
    uint32_t r; asm("cvt.rna.tf32.f32 %0, %1;" : "=r"(r) : "f"(x)); return r;
}
// m16n8k8 tf32 warp MMA (sm_80+ PTX: valid on base sm_103, runs on tensor pipe)
static __device__ __forceinline__ void mma8(float* d, const uint32_t* a, const uint32_t* b){
    asm("mma.sync.aligned.m16n8k8.row.col.f32.tf32.tf32.f32 "
        "{%0,%1,%2,%3}, {%4,%5,%6,%7}, {%8,%9}, {%0,%1,%2,%3};"
        : "+f"(d[0]), "+f"(d[1]), "+f"(d[2]), "+f"(d[3])
        : "r"(a[0]), "r"(a[1]), "r"(a[2]), "r"(a[3]), "r"(b[0]), "r"(b[1]));
}

// ---------------------------------------------------------------------------
// Prep: fold embedding into input term (Mx,My,CB), build B fragments.
// Gate permutation: chunk cc (0..15), tile tt (0..1), tile-col c (0..7):
//   unit = 4*cc + c/2, type = 2*tt + c%2, original row j = type*64 + unit.
// Extended B rows: k<64 -> W_hh[j][k]; k=64 Mx; 65 My; 66 CB; 67..71 zero.
// Fragment value at (cc,tt,ks,lane=4*gid+tig, idx): B[k=ks*8+tig+4*idx][n=gid]
// ---------------------------------------------------------------------------
__global__ void vlstm_prep(const float* __restrict__ ew, const float* __restrict__ eb,
                           const float* __restrict__ wih_e, const float* __restrict__ whh_e,
                           const float* __restrict__ bih_e, const float* __restrict__ bhh_e,
                           const float* __restrict__ dw, const float* __restrict__ db,
                           const float* __restrict__ wih_d, const float* __restrict__ whh_d,
                           const float* __restrict__ bih_d, const float* __restrict__ bhh_d)
{
    __shared__ float sMx[256], sMy[256], sCB[256];
    const int j = threadIdx.x;   // 0..255
    for (int ph = 0; ph < 2; ph++) {
        const float* emb_w = ph ? dw : ew;
        const float* emb_b = ph ? db : eb;
        const float* wih   = ph ? wih_d : wih_e;
        const float* whh   = ph ? whh_d : whh_e;
        const float* bih   = ph ? bih_d : bih_e;
        const float* bhh   = ph ? bhh_d : bhh_e;
        float mx = 0.f, my = 0.f, mb = 0.f;
        #pragma unroll 8
        for (int e = 0; e < 64; e++) {
            float wv = wih[j * 64 + e];
            mx += wv * emb_w[e * 2 + 0];
            my += wv * emb_w[e * 2 + 1];
            mb += wv * emb_b[e];
        }
        sMx[j] = mx; sMy[j] = my; sCB[j] = mb + bih[j] + bhh[j];
        __syncthreads();

        for (int q = j; q < WF_N / 2; q += 256) {    // frag-pair id
            int lane = q & 31;
            int ks   = (q >> 5) % 9;
            int tcc  = q / 288;               // cc*2+tt
            int tt = tcc & 1, cc = tcc >> 1;
            int tig = lane & 3, gid = lane >> 2;
            int unit = 4 * cc + (gid >> 1);
            int ty   = 2 * tt + (gid & 1);
            int jj   = ty * 64 + unit;
            #pragma unroll
            for (int idx = 0; idx < 2; idx++) {
                int k = ks * 8 + tig + idx * 4;
                float v = (k < 64) ? whh[jj * 64 + k]
                        : (k == 64) ? sMx[jj]
                        : (k == 65) ? sMy[jj]
                        : (k == 66) ? sCB[jj] : 0.f;
                g_wF[ph][q * 2 + idx] = t32(v);
            }
        }
        __syncthreads();
    }
}

// ---------------------------------------------------------------------------
// One LSTM step (all warps independent; only __syncwarp inside).
// hcO/hnO = float-offsets of current/next h tiles in smem.
// ---------------------------------------------------------------------------
template <bool DEC>
static __device__ __forceinline__ void lstm_step(
    float* __restrict__ sm, const uint32_t* __restrict__ WF,
    const float* __restrict__ sP0, const float* __restrict__ sP1,
    int hcO, int hnO,
    int wbase, int gbase, int gid, int tig,
    const float* __restrict__ obs_t,     // encoder: input ptr for this t
    float pb0, float pb1,
    float* __restrict__ outp)            // decoder: output ptr for this t
{
    uint32_t* smu = (uint32_t*)sm;

    if (!DEC) {
        if (tig == 0) {
            #pragma unroll
            for (int rb = 0; rb < 2; rb++)
                #pragma unroll
                for (int hi = 0; hi < 2; hi++) {
                    int off = rb * 16 + gid + hi * 8;
                    float2 p = *(const float2*)(obs_t + (size_t)(gbase + off) * 2);
                    smu[hcO + (wbase + off) * HSTR + 64] = t32(p.x);
                    smu[hcO + (wbase + off) * HSTR + 65] = t32(p.y);
                }
        }
    }
    __syncwarp();

    // ---- A fragments: 2 row-blocks x 9 k-steps x 4 regs ----
    uint32_t A[2][9][4];
    #pragma unroll
    for (int rb = 0; rb < 2; rb++) {
        const uint32_t* rp = smu + hcO + (wbase + rb * 16 + gid) * HSTR + tig;
        #pragma unroll
        for (int ks = 0; ks < 9; ks++) {
            A[rb][ks][0] = rp[ks * 8];
            A[rb][ks][1] = rp[ks * 8 + 8 * HSTR];
            A[rb][ks][2] = rp[ks * 8 + 4];
            A[rb][ks][3] = rp[ks * 8 + 4 + 8 * HSTR];
        }
    }

    float rxy[2][2][2];
    if (DEC) {
        #pragma unroll
        for (int rb = 0; rb < 2; rb++)
            #pragma unroll
            for (int hi = 0; hi < 2; hi++) { rxy[rb][hi][0] = 0.f; rxy[rb][hi][1] = 0.f; }
    }

    const int lane2 = (gid * 4 + tig) * 2;

    #pragma unroll 1
    for (int cc = 0; cc < 16; cc++) {
        // B fragments for this chunk (pre-shuffled, conflict-free LDS.64)
        uint32_t Bf[2][9][2];
        #pragma unroll
        for (int tt = 0; tt < 2; tt++)
            #pragma unroll
            for (int ks = 0; ks < 9; ks++) {
                uint2 v = *(const uint2*)(WF + ((cc * 2 + tt) * 9 + ks) * 64 + lane2);
                Bf[tt][ks][0] = v.x; Bf[tt][ks][1] = v.y;
            }

        const int u = 4 * cc + tig;
        float* cB = g_cS + (size_t)u * BATCHN + gbase;
        float cold[2][2];
        #pragma unroll
        for (int rb = 0; rb < 2; rb++)
            #pragma unroll
            for (int hi = 0; hi < 2; hi++)
                cold[rb][hi] = cB[rb * 16 + gid + hi * 8];

        float acc[2][2][4];
        #pragma unroll
        for (int rb = 0; rb < 2; rb++)
            #pragma unroll
            for (int tt = 0; tt < 2; tt++)
                #pragma unroll
                for (int x = 0; x < 4; x++) acc[rb][tt][x] = 0.f;

        #pragma unroll
        for (int rb = 0; rb < 2; rb++)
            #pragma unroll
            for (int tt = 0; tt < 2; tt++)
                #pragma unroll
                for (int ks = 0; ks < 9; ks++)
                    mma8(acc[rb][tt], A[rb][ks], Bf[tt][ks]);

        float p0 = 0.f, p1 = 0.f;
        if (DEC) { p0 = sP0[u]; p1 = sP1[u]; }

        // epilogue: tile0 cols (2tig,2tig+1) = (i,f) of unit u; tile1 = (g,o)
        #pragma unroll
        for (int rb = 0; rb < 2; rb++)
            #pragma unroll
            for (int hi = 0; hi < 2; hi++) {
                float iv = acc[rb][0][hi * 2 + 0];
                float fv = acc[rb][0][hi * 2 + 1];
                float gv = acc[rb][1][hi * 2 + 0];
                float ov = acc[rb][1][hi * 2 + 1];
                float cn = fmaf(sga(fv), cold[rb][hi], sga(iv) * tha(gv));
                cB[rb * 16 + gid + hi * 8] = cn;
                float hn = sga(ov) * tha(cn);
                smu[hnO + (wbase + rb * 16 + gid + hi * 8) * HSTR + u] = t32(hn);
                if (DEC) {
                    rxy[rb][hi][0] = fmaf(hn, p0, rxy[rb][hi][0]);
                    rxy[rb][hi][1] = fmaf(hn, p1, rxy[rb][hi][1]);
                }
            }
    }

    if (DEC) {
        // reduce over the 4 tig lanes of each group
        #pragma unroll
        for (int rb = 0; rb < 2; rb++)
            #pragma unroll
            for (int hi = 0; hi < 2; hi++)
                #pragma unroll
                for (int d = 0; d < 2; d++) {
                    float v = rxy[rb][hi][d];
                    v += __shfl_xor_sync(0xffffffffu, v, 1);
                    v += __shfl_xor_sync(0xffffffffu, v, 2);
                    rxy[rb][hi][d] = v;
                }
        if (tig == 0) {
            #pragma unroll
            for (int rb = 0; rb < 2; rb++)
                #pragma unroll
                for (int hi = 0; hi < 2; hi++) {
                    int off = rb * 16 + gid + hi * 8;
                    float rx = rxy[rb][hi][0] + pb0;
                    float ry = rxy[rb][hi][1] + pb1;
                    smu[hnO + (wbase + off) * HSTR + 64] = t32(rx);
                    smu[hnO + (wbase + off) * HSTR + 65] = t32(ry);
                    *(float2*)(outp + (size_t)(gbase + off) * 2) = make_float2(rx, ry);
                }
        }
    }
}

// ---------------------------------------------------------------------------
// Main kernel
// ---------------------------------------------------------------------------
__global__ void __launch_bounds__(BLK, 1)
vlstm_main(const float* __restrict__ obs_rel,
           const float* __restrict__ h2p_w, const float* __restrict__ h2p_b,
           float* __restrict__ out)
{
    extern __shared__ float sm[];
    uint32_t* WF = (uint32_t*)(sm + SF_WF);
    float* sP0 = sm + SF_P0;
    float* sP1 = sm + SF_P1;

    const int tid  = threadIdx.x;
    const int wid  = tid >> 5;
    const int lane = tid & 31;
    const int gid  = lane >> 2;
    const int tig  = lane & 3;
    const int wbase = wid * 32;                       // CTA-local elem base
    const int gbase = blockIdx.x * EPB + wbase;       // global elem base

    // ---- init: weights, zero h tiles ----
    for (int i = tid; i < WF_N; i += BLK) WF[i] = g_wF[0][i];
    for (int i = tid; i < 2 * EPB * HSTR; i += BLK) sm[SF_H0 + i] = 0.f;
    if (tid < 64) { sP0[tid] = h2p_w[tid]; sP1[tid] = h2p_w[64 + tid]; }
    __syncthreads();
    for (int r = tid; r < EPB; r += BLK) {            // constant-1 column (k=66)
        sm[SF_H0 + r * HSTR + 66] = 1.0f;
        sm[SF_H1 + r * HSTR + 66] = 1.0f;
    }
    #pragma unroll 1
    for (int cc = 0; cc < 16; cc++) {                 // zero this thread's c slots
        int u = 4 * cc + tig;
        float* cB = g_cS + (size_t)u * BATCHN + gbase;
        #pragma unroll
        for (int rb = 0; rb < 2; rb++)
            #pragma unroll
            for (int hi = 0; hi < 2; hi++) cB[rb * 16 + gid + hi * 8] = 0.f;
    }
    __syncthreads();

    int hc = SF_H0, hn = SF_H1;

    // ---- encoder: 8 steps ----
    #pragma unroll 1
    for (int t = 0; t < OBS_LEN; t++) {
        lstm_step<false>(sm, WF, sP0, sP1, hc, hn, wbase, gbase, gid, tig,
                         obs_rel + (size_t)t * BATCHN * 2, 0.f, 0.f, nullptr);
        int tmp = hc; hc = hn; hn = tmp;
    }

    // ---- phase swap: decoder weights, reset c, seed px/py = obs[7] ----
    __syncthreads();
    for (int i = tid; i < WF_N; i += BLK) WF[i] = g_wF[1][i];
    #pragma unroll 1
    for (int cc = 0; cc < 16; cc++) {
        int u = 4 * cc + tig;
        float* cB = g_cS + (size_t)u * BATCHN + gbase;
        #pragma unroll
        for (int rb = 0; rb < 2; rb++)
            #pragma unroll
            for (int hi = 0; hi < 2; hi++) cB[rb * 16 + gid + hi * 8] = 0.f;
    }
    if (tig == 0) {
        uint32_t* smu = (uint32_t*)sm;
        #pragma unroll
        for (int rb = 0; rb < 2; rb++)
            #pragma unroll
            for (int hi = 0; hi < 2; hi++) {
                int off = rb * 16 + gid + hi * 8;
                float2 p = *(const float2*)(obs_rel + (size_t)(7 * BATCHN + gbase + off) * 2);
                smu[hc + (wbase + off) * HSTR + 64] = t32(p.x);
                smu[hc + (wbase + off) * HSTR + 65] = t32(p.y);
            }
    }
    __syncthreads();

    const float pb0 = h2p_b[0], pb1 = h2p_b[1];

    // ---- decoder: 12 steps ----
    #pragma unroll 1
    for (int t = 0; t < PRED_LEN; t++) {
        lstm_step<true>(sm, WF, sP0, sP1, hc, hn, wbase, gbase, gid, tig,
                        nullptr, pb0, pb1, out + (size_t)t * BATCHN * 2);
        int tmp = hc; hc = hn; hn = tmp;
    }
}

// ---------------------------------------------------------------------------
// Launch
// ---------------------------------------------------------------------------
extern "C" void kernel_launch(void* const* d_in, const int* in_sizes, int n_in,
                              void* d_out, int out_size)
{
    // metadata order: 0 obs_traj(unused), 1 obs_traj_rel,
    // 2..7 enc{emb_w,emb_b,w_ih,w_hh,b_ih,b_hh}, 8..13 dec{...}, 14 h2p_w, 15 h2p_b
    const float* obs_rel = (const float*)d_in[1];

    vlstm_prep<<<1, 256>>>(
        (const float*)d_in[2],  (const float*)d_in[3],
        (const float*)d_in[4],  (const float*)d_in[5],
        (const float*)d_in[6],  (const float*)d_in[7],
        (const float*)d_in[8],  (const float*)d_in[9],
        (const float*)d_in[10], (const float*)d_in[11],
        (const float*)d_in[12], (const float*)d_in[13]);

    const size_t smem = (size_t)SF_TOT * sizeof(float);   // ~217 KB
    cudaFuncSetAttribute(vlstm_main, cudaFuncAttributeMaxDynamicSharedMemorySize, (int)smem);
    vlstm_main<<<BATCHN / EPB, BLK, smem>>>(
        obs_rel, (const float*)d_in[14], (const float*)d_in[15], (float*)d_out);
}

// round 12
// speedup vs baseline: 3.9908x; 1.1169x over previous
#include <cuda_runtime.h>
#include <cstdint>

#define OBS_LEN 8
#define PRED_LEN 12
#define BATCHN 65536
#define BLK 256
#define EPB 256          // elems per CTA -> grid = 256
#define HSTR 68          // row stride (floats) for h and c tiles: 64 + pad
#define WF_N 16384       // frag words/phase: 16cc * 2tt * 8ks * 64

// W in mma-B-fragment order (tf32 bits); packed input-term table [u<64][ty][mx,my,cb]
__device__ uint32_t g_wF[2][WF_N];
__device__ float    g_cmP[2][64 * 12];

// ---- smem float-offsets ----
#define SF_WF 0              // 16384
#define SF_H  16384          // 256*68 = 17408
#define SF_C  33792          // 17408
#define SF_CM 51200          // 768 (64*12)
#define SF_P0 51968          // 64
#define SF_P1 52032          // 64
#define SF_TOT 52096         // *4 = 208384 B

static __device__ __forceinline__ float tha(float x){
    float r; asm("tanh.approx.f32 %0, %1;" : "=f"(r) : "f"(x)); return r;
}
static __device__ __forceinline__ float sga(float x){
    return fmaf(0.5f, tha(0.5f * x), 0.5f);
}
static __device__ __forceinline__ uint32_t t32(float x){
    uint32_t r; asm("cvt.rna.tf32.f32 %0, %1;" : "=r"(r) : "f"(x)); return r;
}
static __device__ __forceinline__ void mma8(float* d, const uint32_t* a, const uint32_t* b){
    asm("mma.sync.aligned.m16n8k8.row.col.f32.tf32.tf32.f32 "
        "{%0,%1,%2,%3}, {%4,%5,%6,%7}, {%8,%9}, {%0,%1,%2,%3};"
        : "+f"(d[0]), "+f"(d[1]), "+f"(d[2]), "+f"(d[3])
        : "r"(a[0]), "r"(a[1]), "r"(a[2]), "r"(a[3]), "r"(b[0]), "r"(b[1]));
}

// ---------------------------------------------------------------------------
// Prep: input-term table (per unit u<64: [ty][mx,my,cb]) + B fragments (K=64).
// Gate mapping per chunk cc, tile tt, B n-col g: unit=4cc+(g>>1), ty=2tt+(g&1).
// ---------------------------------------------------------------------------
__global__ void vlstm_prep(const float* __restrict__ ew, const float* __restrict__ eb,
                           const float* __restrict__ wih_e, const float* __restrict__ whh_e,
                           const float* __restrict__ bih_e, const float* __restrict__ bhh_e,
                           const float* __restrict__ dw, const float* __restrict__ db,
                           const float* __restrict__ wih_d, const float* __restrict__ whh_d,
                           const float* __restrict__ bih_d, const float* __restrict__ bhh_d)
{
    __shared__ float sMx[256], sMy[256], sCB[256];
    const int j = threadIdx.x;   // 0..255 = gate row
    for (int ph = 0; ph < 2; ph++) {
        const float* emb_w = ph ? dw : ew;
        const float* emb_b = ph ? db : eb;
        const float* wih   = ph ? wih_d : wih_e;
        const float* whh   = ph ? whh_d : whh_e;
        const float* bih   = ph ? bih_d : bih_e;
        const float* bhh   = ph ? bhh_d : bhh_e;
        float mx = 0.f, my = 0.f, mb = 0.f;
        #pragma unroll 8
        for (int e = 0; e < 64; e++) {
            float wv = wih[j * 64 + e];
            mx += wv * emb_w[e * 2 + 0];
            my += wv * emb_w[e * 2 + 1];
            mb += wv * emb_b[e];
        }
        sMx[j] = mx; sMy[j] = my; sCB[j] = mb + bih[j] + bhh[j];
        __syncthreads();

        // packed table (only u < 64 is meaningful; guard keeps sMx reads in-bounds)
        if (j < 64) {
            const int u = j;
            #pragma unroll
            for (int ty = 0; ty < 4; ty++) {
                g_cmP[ph][u * 12 + ty * 3 + 0] = sMx[ty * 64 + u];
                g_cmP[ph][u * 12 + ty * 3 + 1] = sMy[ty * 64 + u];
                g_cmP[ph][u * 12 + ty * 3 + 2] = sCB[ty * 64 + u];
            }
        }
        // B fragments: word w = q*2+idx, q = ((cc*2+tt)*8+ks)*32 + lane
        for (int q = j; q < WF_N / 2; q += 256) {
            int lane = q & 31;
            int ks   = (q >> 5) & 7;
            int tcc  = q >> 8;
            int tt = tcc & 1, cc = tcc >> 1;
            int tig = lane & 3, gid = lane >> 2;
            int unit = 4 * cc + (gid >> 1);
            int ty   = 2 * tt + (gid & 1);
            int jj   = ty * 64 + unit;
            #pragma unroll
            for (int idx = 0; idx < 2; idx++) {
                int k = ks * 8 + tig + idx * 4;
                g_wF[ph][q * 2 + idx] = t32(whh[jj * 64 + k]);
            }
        }
        __syncthreads();
    }
}

// ---------------------------------------------------------------------------
// One LSTM step. Warp-private rows (wbase..wbase+31). h updated in-place
// (A fragments fully register-resident before any overwrite; __syncwarp
// fences). c in smem. px/py in registers. Decoder chains inputs via shfl.
// ---------------------------------------------------------------------------
template <bool DEC>
static __device__ __forceinline__ void lstm_step(
    float* __restrict__ sm, int wbase, int gid, int tig,
    float px[2][2], float py[2][2],
    float pb0, float pb1,
    float* __restrict__ outp, int gbase)
{
    uint32_t* smu = (uint32_t*)sm;

    // ---- A fragments (old h): 2 row-blocks x 8 k-steps x 4 regs ----
    uint32_t A[2][8][4];
    #pragma unroll
    for (int rb = 0; rb < 2; rb++) {
        const uint32_t* rp = smu + SF_H + (wbase + rb * 16 + gid) * HSTR + tig;
        #pragma unroll
        for (int ks = 0; ks < 8; ks++) {
            A[rb][ks][0] = rp[ks * 8];
            A[rb][ks][1] = rp[ks * 8 + 8 * HSTR];
            A[rb][ks][2] = rp[ks * 8 + 4];
            A[rb][ks][3] = rp[ks * 8 + 8 * HSTR + 4];
        }
    }
    __syncwarp();   // all lanes' A reads done before any lane overwrites h

    float rx[2][2], ry[2][2];
    if (DEC) {
        #pragma unroll
        for (int rb = 0; rb < 2; rb++)
            #pragma unroll
            for (int hi = 0; hi < 2; hi++) { rx[rb][hi] = 0.f; ry[rb][hi] = 0.f; }
    }
    const int lane2 = (gid * 4 + tig) * 2;

    #pragma unroll 1
    for (int cc = 0; cc < 16; cc++) {
        const int u = 4 * cc + tig;

        // input-term table (3 x LDS.128, broadcast across gid)
        float4 cmi = *(const float4*)(sm + SF_CM + u * 12);
        float4 cmf = *(const float4*)(sm + SF_CM + u * 12 + 4);
        float4 cmg = *(const float4*)(sm + SF_CM + u * 12 + 8);

        // c prefetch (conflict-free LDS.32: bank = (4*off+u)%32, all distinct)
        float cold[2][2];
        #pragma unroll
        for (int rb = 0; rb < 2; rb++)
            #pragma unroll
            for (int hi = 0; hi < 2; hi++)
                cold[rb][hi] = sm[SF_C + (wbase + rb * 16 + gid + hi * 8) * HSTR + u];

        float p0 = 0.f, p1 = 0.f;
        if (DEC) { p0 = sm[SF_P0 + u]; p1 = sm[SF_P1 + u]; }

        // B fragments for this chunk (pre-shuffled, LDS.64 conflict-free)
        uint32_t Bf[2][8][2];
        #pragma unroll
        for (int tt = 0; tt < 2; tt++)
            #pragma unroll
            for (int ks = 0; ks < 8; ks++) {
                uint2 v = *(const uint2*)(smu + SF_WF + ((cc * 2 + tt) * 8 + ks) * 64 + lane2);
                Bf[tt][ks][0] = v.x; Bf[tt][ks][1] = v.y;
            }

        float acc[2][2][4];
        #pragma unroll
        for (int rb = 0; rb < 2; rb++)
            #pragma unroll
            for (int tt = 0; tt < 2; tt++)
                #pragma unroll
                for (int x = 0; x < 4; x++) acc[rb][tt][x] = 0.f;

        #pragma unroll
        for (int rb = 0; rb < 2; rb++)
            #pragma unroll
            for (int tt = 0; tt < 2; tt++)
                #pragma unroll
                for (int ks = 0; ks < 8; ks++)
                    mma8(acc[rb][tt], A[rb][ks], Bf[tt][ks]);

        // epilogue: tile0 cols (2tig,2tig+1)=(i,f), tile1=(g,o) of unit u
        #pragma unroll
        for (int rb = 0; rb < 2; rb++)
            #pragma unroll
            for (int hi = 0; hi < 2; hi++) {
                const int off = wbase + rb * 16 + gid + hi * 8;
                float pxl = px[rb][hi], pyl = py[rb][hi];
                float iv = acc[rb][0][2*hi+0] + fmaf(cmi.x, pxl, fmaf(cmi.y, pyl, cmi.z));
                float fv = acc[rb][0][2*hi+1] + fmaf(cmi.w, pxl, fmaf(cmf.x, pyl, cmf.y));
                float gv = acc[rb][1][2*hi+0] + fmaf(cmf.z, pxl, fmaf(cmf.w, pyl, cmg.x));
                float ov = acc[rb][1][2*hi+1] + fmaf(cmg.y, pxl, fmaf(cmg.z, pyl, cmg.w));
                float cn = fmaf(sga(fv), cold[rb][hi], sga(iv) * tha(gv));
                sm[SF_C + off * HSTR + u] = cn;
                float hn = sga(ov) * tha(cn);
                smu[SF_H + off * HSTR + u] = t32(hn);
                if (DEC) {
                    rx[rb][hi] = fmaf(hn, p0, rx[rb][hi]);
                    ry[rb][hi] = fmaf(hn, p1, ry[rb][hi]);
                }
            }
    }

    if (DEC) {
        #pragma unroll
        for (int rb = 0; rb < 2; rb++)
            #pragma unroll
            for (int hi = 0; hi < 2; hi++) {
                float vx = rx[rb][hi], vy = ry[rb][hi];
                vx += __shfl_xor_sync(0xffffffffu, vx, 1);
                vx += __shfl_xor_sync(0xffffffffu, vx, 2);
                vy += __shfl_xor_sync(0xffffffffu, vy, 1);
                vy += __shfl_xor_sync(0xffffffffu, vy, 2);
                vx += pb0; vy += pb1;
                px[rb][hi] = vx; py[rb][hi] = vy;   // next step's input (in-reg)
                if (tig == 0) {
                    const int off = rb * 16 + gid + hi * 8;
                    *(float2*)(outp + (size_t)(gbase + off) * 2) = make_float2(vx, vy);
                }
            }
    }
    __syncwarp();   // h/c stores visible before next step's A loads
}

// ---------------------------------------------------------------------------
// Main kernel
// ---------------------------------------------------------------------------
__global__ void __launch_bounds__(BLK, 1)
vlstm_main(const float* __restrict__ obs_rel,
           const float* __restrict__ h2p_w, const float* __restrict__ h2p_b,
           float* __restrict__ out)
{
    extern __shared__ float sm[];
    uint32_t* WF = (uint32_t*)(sm + SF_WF);

    const int tid  = threadIdx.x;
    const int wid  = tid >> 5;
    const int lane = tid & 31;
    const int gid  = lane >> 2;
    const int tig  = lane & 3;
    const int wbase = wid * 32;
    const int gbase = blockIdx.x * EPB + wbase;

    // ---- init: encoder weights/table, h2p, zero h and c ----
    for (int i = tid; i < WF_N; i += BLK) WF[i] = g_wF[0][i];
    if (tid < 192) {
        sm[SF_CM + tid] = g_cmP[0][tid];
        sm[SF_CM + 192 + tid] = g_cmP[0][192 + tid];
        sm[SF_CM + 384 + tid] = g_cmP[0][384 + tid];
        sm[SF_CM + 576 + tid] = g_cmP[0][576 + tid];
    }
    if (tid < 64) { sm[SF_P0 + tid] = h2p_w[tid]; sm[SF_P1 + tid] = h2p_w[64 + tid]; }
    for (int i = tid; i < EPB * HSTR; i += BLK) { sm[SF_H + i] = 0.f; sm[SF_C + i] = 0.f; }
    __syncthreads();

    float px[2][2], py[2][2];

    // ---- encoder: 8 steps ----
    #pragma unroll 1
    for (int t = 0; t < OBS_LEN; t++) {
        #pragma unroll
        for (int rb = 0; rb < 2; rb++)
            #pragma unroll
            for (int hi = 0; hi < 2; hi++) {
                int off = rb * 16 + gid + hi * 8;
                float2 p = *(const float2*)(obs_rel + (size_t)(t * BATCHN + gbase + off) * 2);
                px[rb][hi] = p.x; py[rb][hi] = p.y;
            }
        lstm_step<false>(sm, wbase, gid, tig, px, py, 0.f, 0.f, nullptr, gbase);
    }

    // ---- phase swap: decoder weights/table, reset c ----
    __syncthreads();
    for (int i = tid; i < WF_N; i += BLK) WF[i] = g_wF[1][i];
    if (tid < 192) {
        sm[SF_CM + tid] = g_cmP[1][tid];
        sm[SF_CM + 192 + tid] = g_cmP[1][192 + tid];
        sm[SF_CM + 384 + tid] = g_cmP[1][384 + tid];
        sm[SF_CM + 576 + tid] = g_cmP[1][576 + tid];
    }
    for (int i = tid; i < EPB * HSTR; i += BLK) sm[SF_C + i] = 0.f;
    __syncthreads();

    const float pb0 = h2p_b[0], pb1 = h2p_b[1];
    #pragma unroll
    for (int rb = 0; rb < 2; rb++)
        #pragma unroll
        for (int hi = 0; hi < 2; hi++) {
            int off = rb * 16 + gid + hi * 8;
            float2 p = *(const float2*)(obs_rel + (size_t)(7 * BATCHN + gbase + off) * 2);
            px[rb][hi] = p.x; py[rb][hi] = p.y;
        }

    // ---- decoder: 12 steps (inputs chained in registers) ----
    #pragma unroll 1
    for (int t = 0; t < PRED_LEN; t++) {
        lstm_step<true>(sm, wbase, gid, tig, px, py, pb0, pb1,
                        out + (size_t)t * BATCHN * 2, gbase);
    }
}

// ---------------------------------------------------------------------------
// Launch
// ---------------------------------------------------------------------------
extern "C" void kernel_launch(void* const* d_in, const int* in_sizes, int n_in,
                              void* d_out, int out_size)
{
    // metadata order: 0 obs_traj(unused), 1 obs_traj_rel,
    // 2..7 enc{emb_w,emb_b,w_ih,w_hh,b_ih,b_hh}, 8..13 dec{...}, 14 h2p_w, 15 h2p_b
    const float* obs_rel = (const float*)d_in[1];

    vlstm_prep<<<1, 256>>>(
        (const float*)d_in[2],  (const float*)d_in[3],
        (const float*)d_in[4],  (const float*)d_in[5],
        (const float*)d_in[6],  (const float*)d_in[7],
        (const float*)d_in[8],  (const float*)d_in[9],
        (const float*)d_in[10], (const float*)d_in[11],
        (const float*)d_in[12], (const float*)d_in[13]);

    const size_t smem = (size_t)SF_TOT * sizeof(float);   // ~208 KB
    cudaFuncSetAttribute(vlstm_main, cudaFuncAttributeMaxDynamicSharedMemorySize, (int)smem);
    vlstm_main<<<BATCHN / EPB, BLK, smem>>>(
        obs_rel, (const float*)d_in[14], (const float*)d_in[15], (float*)d_out);
}